// round 7
// baseline (speedup 1.0000x reference)
#include <cuda_runtime.h>

#define N_NODES 50000
#define E_MAX   1600000

// ---------------- scratch (static device globals; no allocation) -------------
__device__ int    g_deg[N_NODES];        // includes self loop
__device__ float  g_dis[N_NODES];
__device__ int    g_src[E_MAX];
__device__ int    g_dst[E_MAX];
__device__ int    g_offs[N_NODES + 1];   // CSR offsets by dst (real edges only)
__device__ int    g_cur[N_NODES];        // bucket cursors
__device__ int    g_csr_src[E_MAX];      // src ids grouped by dst
__device__ float4 g_hs [N_NODES * 16];   // dis[src]-scaled x@W1, 64 f32/node
__device__ float4 g_hs2[N_NODES *  8];   // dis-scaled h@W2, 32 f32/node

// ---------------- prep --------------------------------------------------------
__global__ void k_init_deg() {
    int i = blockIdx.x * blockDim.x + threadIdx.x;
    if (i < N_NODES) g_deg[i] = 1;   // self loop
}

// dtype layout detect (per block, from 256 sampled odd words) + edge parse.
// int64 layout: odd int32 words are high words == 0. int32: random ids.
__global__ void k_prep_edges(const int* __restrict__ p, int E) {
    __shared__ int s_nonzero;
    if (threadIdx.x == 0) s_nonzero = 0;
    __syncthreads();
    if (threadIdx.x < 256) {
        if (p[2 * threadIdx.x + 1] != 0) atomicOr(&s_nonzero, 1);
    }
    __syncthreads();
    int i64 = (s_nonzero == 0);

    int e = blockIdx.x * blockDim.x + threadIdx.x;
    if (e >= E) return;
    int s, d;
    if (i64) { s = p[2 * e]; d = p[2 * (E + e)]; }
    else     { s = p[e];     d = p[E + e]; }
    if ((unsigned)s >= N_NODES) s = 0;
    if ((unsigned)d >= N_NODES) d = 0;
    g_src[e] = s;
    g_dst[e] = d;
    atomicAdd(&g_deg[d], 1);
}

// ---------------- scan of (deg-1) -> offs/cur, fused dis; single block -------
#define SCAN_T 1024
#define SCAN_CH ((N_NODES + SCAN_T - 1) / SCAN_T)   // 49
__global__ void k_scan() {
    __shared__ int partial[SCAN_T];
    int t = threadIdx.x;
    int base = t * SCAN_CH;
    int sum = 0;
#pragma unroll 4
    for (int i = 0; i < SCAN_CH; i++) {
        int idx = base + i;
        if (idx < N_NODES) sum += g_deg[idx] - 1;
    }
    partial[t] = sum;
    __syncthreads();
    for (int off = 1; off < SCAN_T; off <<= 1) {
        int v = (t >= off) ? partial[t - off] : 0;
        __syncthreads();
        partial[t] += v;
        __syncthreads();
    }
    int run = (t == 0) ? 0 : partial[t - 1];
    for (int i = 0; i < SCAN_CH; i++) {
        int idx = base + i;
        if (idx < N_NODES) {
            int dg = g_deg[idx];
            g_offs[idx] = run;
            g_cur[idx]  = run;
            g_dis[idx]  = rsqrtf((float)dg);
            run += dg - 1;
        }
    }
    if (t == SCAN_T - 1) g_offs[N_NODES] = partial[SCAN_T - 1];
}

// ---------------- bucket edges by dst ----------------------------------------
__global__ void k_bucket(int E) {
    int e = blockIdx.x * blockDim.x + threadIdx.x;
    if (e >= E) return;
    int d = g_dst[e];
    int pos = atomicAdd(&g_cur[d], 1);
    g_csr_src[pos] = g_src[e];
}

// ---------------- GEMM1: hs = dis * (x @ W1) ---------------------------------
__global__ void k_gemm1(const float* __restrict__ x, const float* __restrict__ W) {
    __shared__ float sWT[64 * 132];
    int t = threadIdx.x;
    for (int idx = t; idx < 128 * 64; idx += 128) {
        int k = idx >> 6, c = idx & 63;
        sWT[c * 132 + k] = W[idx];
    }
    __syncthreads();

    int rbase = blockIdx.x * 64 + (t >> 3);
    int cbase = t & 7;
    float acc[4][8];
#pragma unroll
    for (int i = 0; i < 4; i++)
#pragma unroll
        for (int j = 0; j < 8; j++) acc[i][j] = 0.f;

    for (int k = 0; k < 128; k += 4) {
        float4 b[8];
#pragma unroll
        for (int j = 0; j < 8; j++)
            b[j] = *(const float4*)&sWT[(cbase + 8 * j) * 132 + k];
#pragma unroll
        for (int i = 0; i < 4; i++) {
            int r = rbase + 16 * i;
            float4 a = (r < N_NODES) ? *(const float4*)&x[r * 128 + k]
                                     : make_float4(0.f, 0.f, 0.f, 0.f);
#pragma unroll
            for (int j = 0; j < 8; j++) {
                acc[i][j] += a.x * b[j].x;
                acc[i][j] += a.y * b[j].y;
                acc[i][j] += a.z * b[j].z;
                acc[i][j] += a.w * b[j].w;
            }
        }
    }

    float* hs = (float*)g_hs;
#pragma unroll
    for (int i = 0; i < 4; i++) {
        int r = rbase + 16 * i;
        if (r < N_NODES) {
            float dv = g_dis[r];
#pragma unroll
            for (int j = 0; j < 8; j++)
                hs[r * 64 + cbase + 8 * j] = dv * acc[i][j];
        }
    }
}

// ---------------- gather layer 1 (+tanh fused), float4 lanes -----------------
// 16 threads per node, each owns one float4 of the 64-wide row.
__global__ void k_gather1(float* __restrict__ hout) {
    int tid = blockIdx.x * 256 + threadIdx.x;
    int g = tid >> 4;
    if (g >= N_NODES) return;
    int t = tid & 15;
    const float4* __restrict__ hs = g_hs;
    const int* __restrict__ cs = g_csr_src;

    float4 acc = hs[g * 16 + t];           // self-loop message
    int j   = g_offs[g];
    int end = g_offs[g + 1];
    for (; j + 7 < end; j += 8) {
        int s0 = cs[j],     s1 = cs[j + 1], s2 = cs[j + 2], s3 = cs[j + 3];
        int s4 = cs[j + 4], s5 = cs[j + 5], s6 = cs[j + 6], s7 = cs[j + 7];
        float4 a0 = hs[s0 * 16 + t], a1 = hs[s1 * 16 + t];
        float4 a2 = hs[s2 * 16 + t], a3 = hs[s3 * 16 + t];
        float4 a4 = hs[s4 * 16 + t], a5 = hs[s5 * 16 + t];
        float4 a6 = hs[s6 * 16 + t], a7 = hs[s7 * 16 + t];
        acc.x += a0.x + a1.x + a2.x + a3.x + a4.x + a5.x + a6.x + a7.x;
        acc.y += a0.y + a1.y + a2.y + a3.y + a4.y + a5.y + a6.y + a7.y;
        acc.z += a0.z + a1.z + a2.z + a3.z + a4.z + a5.z + a6.z + a7.z;
        acc.w += a0.w + a1.w + a2.w + a3.w + a4.w + a5.w + a6.w + a7.w;
    }
    for (; j < end; j++) {
        float4 a = hs[cs[j] * 16 + t];
        acc.x += a.x; acc.y += a.y; acc.z += a.z; acc.w += a.w;
    }

    float dv = g_dis[g];
    float4 o;
    o.x = tanhf(dv * acc.x);
    o.y = tanhf(dv * acc.y);
    o.z = tanhf(dv * acc.z);
    o.w = tanhf(dv * acc.w);
    ((float4*)hout)[g * 16 + t] = o;
}

// ---------------- GEMM2: hs2 = dis * (h @ W2) --------------------------------
__global__ void k_gemm2(const float* __restrict__ h, const float* __restrict__ W) {
    __shared__ float sWT[32 * 68];
    int t = threadIdx.x;
    for (int idx = t; idx < 64 * 32; idx += 128) {
        int k = idx >> 5, c = idx & 31;
        sWT[c * 68 + k] = W[idx];
    }
    __syncthreads();

    int rbase = blockIdx.x * 64 + (t >> 3);
    int cbase = t & 7;
    float acc[4][4];
#pragma unroll
    for (int i = 0; i < 4; i++)
#pragma unroll
        for (int j = 0; j < 4; j++) acc[i][j] = 0.f;

    for (int k = 0; k < 64; k += 4) {
        float4 b[4];
#pragma unroll
        for (int j = 0; j < 4; j++)
            b[j] = *(const float4*)&sWT[(cbase + 8 * j) * 68 + k];
#pragma unroll
        for (int i = 0; i < 4; i++) {
            int r = rbase + 16 * i;
            float4 a = (r < N_NODES) ? *(const float4*)&h[r * 64 + k]
                                     : make_float4(0.f, 0.f, 0.f, 0.f);
#pragma unroll
            for (int j = 0; j < 4; j++) {
                acc[i][j] += a.x * b[j].x;
                acc[i][j] += a.y * b[j].y;
                acc[i][j] += a.z * b[j].z;
                acc[i][j] += a.w * b[j].w;
            }
        }
    }

    float* hs2 = (float*)g_hs2;
#pragma unroll
    for (int i = 0; i < 4; i++) {
        int r = rbase + 16 * i;
        if (r < N_NODES) {
            float dv = g_dis[r];
#pragma unroll
            for (int j = 0; j < 4; j++)
                hs2[r * 32 + cbase + 8 * j] = dv * acc[i][j];
        }
    }
}

// ---------------- gather layer 2 (+final scale fused), float4 lanes ----------
// 8 threads per node, each owns one float4 of the 32-wide row.
__global__ void k_gather2(float* __restrict__ out) {
    int tid = blockIdx.x * 256 + threadIdx.x;
    int g = tid >> 3;
    if (g >= N_NODES) return;
    int t = tid & 7;
    const float4* __restrict__ hs2 = g_hs2;
    const int* __restrict__ cs = g_csr_src;

    float4 acc = hs2[g * 8 + t];
    int j   = g_offs[g];
    int end = g_offs[g + 1];
    for (; j + 7 < end; j += 8) {
        int s0 = cs[j],     s1 = cs[j + 1], s2 = cs[j + 2], s3 = cs[j + 3];
        int s4 = cs[j + 4], s5 = cs[j + 5], s6 = cs[j + 6], s7 = cs[j + 7];
        float4 a0 = hs2[s0 * 8 + t], a1 = hs2[s1 * 8 + t];
        float4 a2 = hs2[s2 * 8 + t], a3 = hs2[s3 * 8 + t];
        float4 a4 = hs2[s4 * 8 + t], a5 = hs2[s5 * 8 + t];
        float4 a6 = hs2[s6 * 8 + t], a7 = hs2[s7 * 8 + t];
        acc.x += a0.x + a1.x + a2.x + a3.x + a4.x + a5.x + a6.x + a7.x;
        acc.y += a0.y + a1.y + a2.y + a3.y + a4.y + a5.y + a6.y + a7.y;
        acc.z += a0.z + a1.z + a2.z + a3.z + a4.z + a5.z + a6.z + a7.z;
        acc.w += a0.w + a1.w + a2.w + a3.w + a4.w + a5.w + a6.w + a7.w;
    }
    for (; j < end; j++) {
        float4 a = hs2[cs[j] * 8 + t];
        acc.x += a.x; acc.y += a.y; acc.z += a.z; acc.w += a.w;
    }

    float dv = g_dis[g];
    float4 o;
    o.x = dv * acc.x; o.y = dv * acc.y; o.z = dv * acc.z; o.w = dv * acc.w;
    ((float4*)out)[g * 8 + t] = o;
}

// ---------------- launch ------------------------------------------------------
extern "C" void kernel_launch(void* const* d_in, const int* in_sizes, int n_in,
                              void* d_out, int out_size) {
    const float* x  = (const float*)d_in[0];
    const int*   ei = (const int*)d_in[1];
    const float* W1 = (const float*)d_in[2];
    const float* W2 = (const float*)d_in[3];

    float* out  = (float*)d_out;          // [N,32]
    float* hout = out + N_NODES * 32;     // [N,64]

    int E = in_sizes[1] / 2;
    if (E > E_MAX) E = E_MAX;

    k_init_deg<<<(N_NODES + 255) / 256, 256>>>();
    k_prep_edges<<<(E + 255) / 256, 256>>>(ei, E);
    k_scan<<<1, SCAN_T>>>();
    k_bucket<<<(E + 255) / 256, 256>>>(E);

    k_gemm1<<<(N_NODES + 63) / 64, 128>>>(x, W1);
    k_gather1<<<(N_NODES * 16 + 255) / 256, 256>>>(hout);

    k_gemm2<<<(N_NODES + 63) / 64, 128>>>(hout, W2);
    k_gather2<<<(N_NODES * 8 + 255) / 256, 256>>>(out);
}